// round 3
// baseline (speedup 1.0000x reference)
#include <cuda_runtime.h>
#include <cstdint>
#include <cstddef>

#define H    256
#define G    4096
#define BR   64      // rows per GEMM block
#define KC   16      // k-chunk
#define NPB  128     // nodes per scatter block
#define NMAX 500224  // capacity for per-node scratch (N = 500000)

// -------- scratch (device globals: no allocation allowed) --------
__device__ float g_scores[NMAX];   // pass A: scores; pass C onward: exp(score - segmax)
__device__ int   g_segmax[G];      // float bits, valid because values are >= 0
__device__ float g_sumexp[G];
__device__ float g_inv[G];

typedef unsigned long long u64;

// -------- batch dtype detection (int32 vs int64) --------
// batch is sorted, values in [0, 4096). If stored as int64 (little-endian),
// int32 word at odd index N-1 is a high word == 0. If int32, word N-1 is the
// sorted max (≈4095, nonzero w.p. ~1).
__device__ __forceinline__ bool batch_is64(const void* b, int N) {
    return ((const int*)b)[N - 1] == 0;
}
__device__ __forceinline__ int get_batch(const void* b, int i, bool is64) {
    int g = is64 ? (int)((const long long*)b)[i] : ((const int*)b)[i];
    return (int)min((unsigned)g, (unsigned)(G - 1));   // safety clamp
}

__device__ __forceinline__ u64 ffma2(u64 a, u64 b, u64 c) {
    u64 d;
    asm("fma.rn.f32x2 %0, %1, %2, %3;" : "=l"(d) : "l"(a), "l"(b), "l"(c));
    return d;
}
__device__ __forceinline__ float2 unpack2(u64 v) {
    float2 r;
    asm("mov.b64 {%0, %1}, %2;" : "=f"(r.x), "=f"(r.y) : "l"(v));
    return r;
}

// -------- pass 0: zero output + segment buffers --------
__global__ void k_init(float* __restrict__ out, int out_size) {
    int i = blockIdx.x * blockDim.x + threadIdx.x;
    if (i < out_size) out[i] = 0.0f;
    if (i < G) { g_segmax[i] = 0; g_sumexp[i] = 0.0f; }
}

// -------- pass A: scores = tanh(X @ W1 + b1) @ w2, + atomicMax into segmax --------
// Block: 64 rows x 256 cols. 256 threads = 8 warps; warp ty owns rows [ty*8, ty*8+8)
// as 4 f32x2 row-pairs; lane tx owns cols {tx + 32c}. W chunk stored duplicated in
// smem so each lane LDS.64 directly yields the packed {w,w} multiplier.
__global__ __launch_bounds__(256, 2)
void k_gemm_score(const float* __restrict__ x, const void* __restrict__ batch,
                  const float* __restrict__ W1, const float* __restrict__ b1,
                  const float* __restrict__ w2, int N)
{
    __shared__ __align__(16) float xsT[KC][BR + 2];   // transposed x tile [k][row]
    __shared__ __align__(16) float wsd[KC][2 * H];    // duplicated W chunk

    const int t  = threadIdx.x;
    const int tx = t & 31;
    const int ty = t >> 5;
    const int rowbase = blockIdx.x * BR;

    u64 acc[4][8];
#pragma unroll
    for (int p = 0; p < 4; p++)
#pragma unroll
        for (int c = 0; c < 8; c++) acc[p][c] = 0ull;

    for (int k0 = 0; k0 < H; k0 += KC) {
        // --- load x tile (64 x 16) transposed: 256 float4, one per thread ---
        {
            int r = t >> 2;       // 0..63
            int q = t & 3;        // float4 slot within the 16-wide row chunk
            int grow = rowbase + r;
            float4 v = make_float4(0.f, 0.f, 0.f, 0.f);
            if (grow < N)
                v = *reinterpret_cast<const float4*>(x + (size_t)grow * H + k0 + q * 4);
            xsT[q * 4 + 0][r] = v.x;
            xsT[q * 4 + 1][r] = v.y;
            xsT[q * 4 + 2][r] = v.z;
            xsT[q * 4 + 3][r] = v.w;
        }
        // --- load W chunk (16 x 256) duplicated: each value stored twice ---
#pragma unroll
        for (int i = 0; i < 4; i++) {
            int idx = t + 256 * i;      // 0..1023
            int kk  = idx >> 6;         // 0..15
            int c4  = idx & 63;         // float4 index within row
            float4 v = *reinterpret_cast<const float4*>(W1 + (size_t)(k0 + kk) * H + c4 * 4);
            float4* dst = reinterpret_cast<float4*>(&wsd[kk][c4 * 8]);
            dst[0] = make_float4(v.x, v.x, v.y, v.y);
            dst[1] = make_float4(v.z, v.z, v.w, v.w);
        }
        __syncthreads();

#pragma unroll
        for (int kk = 0; kk < KC; kk++) {
            u64 xr[4], wv[8];
#pragma unroll
            for (int p = 0; p < 4; p++)
                xr[p] = *reinterpret_cast<const u64*>(&xsT[kk][ty * 8 + 2 * p]);
#pragma unroll
            for (int c = 0; c < 8; c++)
                wv[c] = *reinterpret_cast<const u64*>(&wsd[kk][(tx + 32 * c) * 2]);
#pragma unroll
            for (int p = 0; p < 4; p++)
#pragma unroll
                for (int c = 0; c < 8; c++)
                    acc[p][c] = ffma2(xr[p], wv[c], acc[p][c]);
        }
        __syncthreads();
    }

    // --- epilogue: tanh, dot with w2, warp-reduce across cols, write + atomicMax ---
    const bool is64 = batch_is64(batch, N);
#pragma unroll
    for (int p = 0; p < 4; p++) {
        float sx = 0.f, sy = 0.f;
#pragma unroll
        for (int c = 0; c < 8; c++) {
            int col = tx + 32 * c;
            float2 a = unpack2(acc[p][c]);
            float bb = __ldg(b1 + col);
            float ww = __ldg(w2 + col);
            sx += tanhf(a.x + bb) * ww;
            sy += tanhf(a.y + bb) * ww;
        }
#pragma unroll
        for (int off = 16; off > 0; off >>= 1) {
            sx += __shfl_xor_sync(0xffffffffu, sx, off);
            sy += __shfl_xor_sync(0xffffffffu, sy, off);
        }
        if (tx == 0) {
            int r0 = rowbase + ty * 8 + 2 * p;
            if (r0 < N) {
                g_scores[r0] = sx;
                if (sx > 0.f) atomicMax(&g_segmax[get_batch(batch, r0, is64)], __float_as_int(sx));
            }
            if (r0 + 1 < N) {
                g_scores[r0 + 1] = sy;
                if (sy > 0.f) atomicMax(&g_segmax[get_batch(batch, r0 + 1, is64)], __float_as_int(sy));
            }
        }
    }
}

// -------- pass C: exp(score - segmax), warp-segmented sum into sumexp --------
__global__ void k_exp_sum(const void* __restrict__ batch, int N)
{
    int i = blockIdx.x * blockDim.x + threadIdx.x;
    int lane = threadIdx.x & 31;
    const bool is64 = batch_is64(batch, N);
    int g = -1;
    float e = 0.f;
    if (i < N) {
        g = get_batch(batch, i, is64);
        float m = __int_as_float(g_segmax[g]);
        e = expf(g_scores[i] - m);
        g_scores[i] = e;   // reuse buffer for exp values
    }
    // segmented inclusive scan over sorted keys
    float v = e;
#pragma unroll
    for (int d = 1; d < 32; d <<= 1) {
        float ov = __shfl_up_sync(0xffffffffu, v, d);
        int   og = __shfl_up_sync(0xffffffffu, g, d);
        if (lane >= d && og == g) v += ov;
    }
    int gn = __shfl_down_sync(0xffffffffu, g, 1);
    if (g >= 0 && (lane == 31 || gn != g))
        atomicAdd(&g_sumexp[g], v);
}

// -------- pass D: reciprocal --------
__global__ void k_inv()
{
    int i = blockIdx.x * blockDim.x + threadIdx.x;
    if (i < G) {
        float s = g_sumexp[i];
        g_inv[i] = (s > 0.f) ? 1.0f / s : 0.f;
    }
}

// -------- pass E: out[g] += x[i] * (exp_i * inv[g]), sorted-batch aware --------
__global__ void k_scatter(const float* __restrict__ x, const void* __restrict__ batch,
                          float* __restrict__ out, int N)
{
    int col = threadIdx.x;             // 256 threads, one column each
    int i0 = blockIdx.x * NPB;
    if (i0 >= N) return;
    int i1 = min(i0 + NPB, N);
    const bool is64 = batch_is64(batch, N);

    int gfirst = get_batch(batch, i0, is64);
    int gcur = gfirst;
    float acc = 0.f;

    for (int i = i0; i < i1; i++) {
        int g = get_batch(batch, i, is64);
        if (g != gcur) {
            // flush: first graph of the block may be shared with the previous
            // block -> atomic; interior graphs are exclusively ours -> plain store
            if (gcur == gfirst) atomicAdd(&out[(size_t)gcur * H + col], acc);
            else                out[(size_t)gcur * H + col] = acc;
            acc = 0.f;
            gcur = g;
        }
        float w = g_scores[i] * g_inv[g];
        acc += x[(size_t)i * H + col] * w;
    }
    // last graph may continue into the next block -> atomic
    atomicAdd(&out[(size_t)gcur * H + col], acc);
}

// -------- launch --------
extern "C" void kernel_launch(void* const* d_in, const int* in_sizes, int n_in,
                              void* d_out, int out_size)
{
    const float* x     = (const float*)d_in[0];
    const void*  batch = (const void*)d_in[1];
    const float* W1    = (const float*)d_in[2];
    const float* b1    = (const float*)d_in[3];
    const float* w2    = (const float*)d_in[4];
    float* out = (float*)d_out;

    int N = in_sizes[1];   // element count of batch = number of nodes

    int initBlocks = (out_size + 255) / 256;
    k_init<<<initBlocks, 256>>>(out, out_size);
    k_gemm_score<<<(N + BR - 1) / BR, 256>>>(x, batch, W1, b1, w2, N);
    k_exp_sum<<<(N + 255) / 256, 256>>>(batch, N);
    k_inv<<<(G + 255) / 256, 256>>>();
    k_scatter<<<(N + NPB - 1) / NPB, H>>>(x, batch, out, N);
}

// round 5
// speedup vs baseline: 2.1002x; 2.1002x over previous
#include <cuda_runtime.h>
#include <cuda_bf16.h>
#include <cstdint>
#include <cstddef>

#define H    256
#define G    4096
#define NPB  128      // nodes per scatter block
#define NMAX 500224   // capacity for per-node scratch (N = 500000)
#define BRM  64       // GEMM tile rows per CTA
#define BK   64       // K chunk (halves)
#define STH  72       // smem row stride in halves (36 words: conflict-free frags)

// -------- scratch (device globals: no allocation allowed) --------
__device__ float g_scores[NMAX];
__device__ int   g_segmax[G];
__device__ float g_sumexp[G];
__device__ float g_inv[G];
__device__ __nv_bfloat16 g_Wt_hi[H * H];   // W1^T hi: [n][k]
__device__ __nv_bfloat16 g_Wt_lo[H * H];   // W1^T lo: [n][k]

// -------- batch dtype detection (int32 vs int64) --------
__device__ __forceinline__ bool batch_is64(const void* b, int N) {
    return ((const int*)b)[N - 1] == 0;
}
__device__ __forceinline__ int get_batch(const void* b, int i, bool is64) {
    int g = is64 ? (int)((const long long*)b)[i] : ((const int*)b)[i];
    return (int)min((unsigned)g, (unsigned)(G - 1));
}

// -------- mma.sync m16n8k16 bf16 (baseline ISA, no 'a' feature needed) --------
__device__ __forceinline__ void mma16816(float* c, const uint32_t* a, const uint32_t* b) {
    asm volatile(
        "mma.sync.aligned.m16n8k16.row.col.f32.bf16.bf16.f32 "
        "{%0,%1,%2,%3}, {%4,%5,%6,%7}, {%8,%9}, {%0,%1,%2,%3};"
        : "+f"(c[0]), "+f"(c[1]), "+f"(c[2]), "+f"(c[3])
        : "r"(a[0]), "r"(a[1]), "r"(a[2]), "r"(a[3]), "r"(b[0]), "r"(b[1]));
}

// SMEM layout (bytes). A/B tiles in halves with row stride STH.
#define SM_A_HI 0
#define SM_A_LO (SM_A_HI + BRM * STH * 2)            // 9216
#define SM_B_HI (SM_A_LO + BRM * STH * 2)            // 18432
#define SM_B_LO (SM_B_HI + H * STH * 2)              // 55296
#define SM_SCB  (SM_B_LO + H * STH * 2)              // 92160
#define SM_TOT  (SM_SCB + 4 * 64 * 4)                // 93184

// -------- pass 0: zero output + segment buffers --------
__global__ void k_init(float* __restrict__ out, int out_size) {
    int i = blockIdx.x * blockDim.x + threadIdx.x;
    if (i < out_size) out[i] = 0.0f;
    if (i < G) { g_segmax[i] = 0; g_sumexp[i] = 0.0f; }
}

// -------- prep: W1 [k][n] fp32 -> transposed bf16 hi/lo [n][k] --------
__global__ void k_prep_w(const float* __restrict__ W1) {
    int k = blockIdx.x, n = threadIdx.x;
    float w = W1[k * H + n];
    __nv_bfloat16 h = __float2bfloat16(w);
    float l = w - __bfloat162float(h);
    g_Wt_hi[n * H + k] = h;
    g_Wt_lo[n * H + k] = __float2bfloat16(l);
}

// -------- pass A: mma.sync GEMM (bf16 split) + fused tanh/w2-dot epilogue --------
__global__ __launch_bounds__(256, 2)
void k_gemm_mma(const float* __restrict__ x, const void* __restrict__ batch,
                const float* __restrict__ b1, const float* __restrict__ w2, int N)
{
    extern __shared__ __align__(16) char smem[];
    const int t    = threadIdx.x;
    const int lane = t & 31;
    const int wid  = t >> 5;
    const int wm   = wid & 1;        // M half (32 rows)
    const int wn   = wid >> 1;       // N quarter (64 cols)
    const int gq   = lane >> 2;      // frag group row/col
    const int tg   = lane & 3;       // frag group lane
    const int rowbase = blockIdx.x * BRM;

    const uint32_t* ash = (const uint32_t*)(smem + SM_A_HI);
    const uint32_t* asl = (const uint32_t*)(smem + SM_A_LO);
    const uint32_t* bsh = (const uint32_t*)(smem + SM_B_HI);
    const uint32_t* bsl = (const uint32_t*)(smem + SM_B_LO);
    float (*scb)[64] = (float(*)[64])(smem + SM_SCB);

    float C[2][8][4];
#pragma unroll
    for (int mt = 0; mt < 2; mt++)
#pragma unroll
        for (int nt = 0; nt < 8; nt++)
#pragma unroll
            for (int r = 0; r < 4; r++) C[mt][nt][r] = 0.f;

    for (int c = 0; c < 4; c++) {
        const int k0 = c * BK;
        // ---- load A chunk: x[rowbase..+64)[k0..k0+64) fp32 -> bf16 hi/lo ----
#pragma unroll
        for (int i = 0; i < 4; i++) {
            int idx = t + i * 256;            // 0..1023
            int r = idx >> 4, q = idx & 15;   // row, float4 slot
            int grow = rowbase + r;
            float4 v = make_float4(0.f, 0.f, 0.f, 0.f);
            if (grow < N)
                v = *reinterpret_cast<const float4*>(x + (size_t)grow * H + k0 + q * 4);
            __nv_bfloat16 h0 = __float2bfloat16(v.x), h1 = __float2bfloat16(v.y);
            __nv_bfloat16 h2 = __float2bfloat16(v.z), h3 = __float2bfloat16(v.w);
            float l0 = v.x - __bfloat162float(h0), l1 = v.y - __bfloat162float(h1);
            float l2 = v.z - __bfloat162float(h2), l3 = v.w - __bfloat162float(h3);
            uint32_t hu0 = ((uint32_t)__bfloat16_as_ushort(h1) << 16) | __bfloat16_as_ushort(h0);
            uint32_t hu1 = ((uint32_t)__bfloat16_as_ushort(h3) << 16) | __bfloat16_as_ushort(h2);
            __nv_bfloat16 g0 = __float2bfloat16(l0), g1 = __float2bfloat16(l1);
            __nv_bfloat16 g2 = __float2bfloat16(l2), g3 = __float2bfloat16(l3);
            uint32_t lu0 = ((uint32_t)__bfloat16_as_ushort(g1) << 16) | __bfloat16_as_ushort(g0);
            uint32_t lu1 = ((uint32_t)__bfloat16_as_ushort(g3) << 16) | __bfloat16_as_ushort(g2);
            uint32_t off = (uint32_t)(r * (STH * 2) + q * 8);   // bytes
            *reinterpret_cast<uint2*>(smem + SM_A_HI + off) = make_uint2(hu0, hu1);
            *reinterpret_cast<uint2*>(smem + SM_A_LO + off) = make_uint2(lu0, lu1);
        }
        // ---- load B chunk: Wt_{hi,lo}[n][k0..k0+64) ----
#pragma unroll
        for (int i = 0; i < 8; i++) {
            int idx = t + i * 256;            // 0..2047
            int n = idx >> 3, q = idx & 7;    // row n, 16B group
            uint32_t off = (uint32_t)(n * (STH * 2) + q * 16);
            *reinterpret_cast<uint4*>(smem + SM_B_HI + off) =
                *reinterpret_cast<const uint4*>(g_Wt_hi + n * H + k0 + q * 8);
            *reinterpret_cast<uint4*>(smem + SM_B_LO + off) =
                *reinterpret_cast<const uint4*>(g_Wt_lo + n * H + k0 + q * 8);
        }
        __syncthreads();

        // ---- compute: 4 k16-steps ----
#pragma unroll
        for (int ks = 0; ks < 4; ks++) {
            const int kw = ks * 8 + tg;       // word offset of this lane's k-pair
            uint32_t Ah[2][4], Al[2][4];
#pragma unroll
            for (int mt = 0; mt < 2; mt++) {
                int r0 = (wm * 32 + mt * 16 + gq) * (STH / 2);
                int r1 = r0 + 8 * (STH / 2);
                Ah[mt][0] = ash[r0 + kw];     Ah[mt][1] = ash[r1 + kw];
                Ah[mt][2] = ash[r0 + kw + 4]; Ah[mt][3] = ash[r1 + kw + 4];
                Al[mt][0] = asl[r0 + kw];     Al[mt][1] = asl[r1 + kw];
                Al[mt][2] = asl[r0 + kw + 4]; Al[mt][3] = asl[r1 + kw + 4];
            }
#pragma unroll
            for (int nt = 0; nt < 8; nt++) {
                int nr = (wn * 64 + nt * 8 + gq) * (STH / 2);
                uint32_t Bh[2], Bl[2];
                Bh[0] = bsh[nr + kw]; Bh[1] = bsh[nr + kw + 4];
                Bl[0] = bsl[nr + kw]; Bl[1] = bsl[nr + kw + 4];
#pragma unroll
                for (int mt = 0; mt < 2; mt++) {
                    mma16816(C[mt][nt], Ah[mt], Bh);
                    mma16816(C[mt][nt], Al[mt], Bh);
                    mma16816(C[mt][nt], Ah[mt], Bl);
                }
            }
        }
        __syncthreads();
    }

    // ---- epilogue: tanh + w2 dot, reduce over frag lanes + N-warps ----
#pragma unroll
    for (int mt = 0; mt < 2; mt++) {
        float p0 = 0.f, p1 = 0.f;     // rows gq, gq+8 of this m-tile
#pragma unroll
        for (int nt = 0; nt < 8; nt++) {
            int col0 = wn * 64 + nt * 8 + tg * 2;
            float bb0 = __ldg(b1 + col0),  bb1 = __ldg(b1 + col0 + 1);
            float ww0 = __ldg(w2 + col0),  ww1 = __ldg(w2 + col0 + 1);
            p0 += tanhf(C[mt][nt][0] + bb0) * ww0 + tanhf(C[mt][nt][1] + bb1) * ww1;
            p1 += tanhf(C[mt][nt][2] + bb0) * ww0 + tanhf(C[mt][nt][3] + bb1) * ww1;
        }
        p0 += __shfl_xor_sync(0xffffffffu, p0, 1);
        p0 += __shfl_xor_sync(0xffffffffu, p0, 2);
        p1 += __shfl_xor_sync(0xffffffffu, p1, 1);
        p1 += __shfl_xor_sync(0xffffffffu, p1, 2);
        if (tg == 0) {
            int row = wm * 32 + mt * 16 + gq;
            scb[wn][row]     = p0;
            scb[wn][row + 8] = p1;
        }
    }
    __syncthreads();
    if (t < 64) {
        float sc = scb[0][t] + scb[1][t] + scb[2][t] + scb[3][t];
        int grow = rowbase + t;
        if (grow < N) {
            g_scores[grow] = sc;
            if (sc > 0.f) {
                const bool is64 = batch_is64(batch, N);
                atomicMax(&g_segmax[get_batch(batch, grow, is64)], __float_as_int(sc));
            }
        }
    }
}

// -------- pass C: exp(score - segmax), warp-segmented sum into sumexp --------
__global__ void k_exp_sum(const void* __restrict__ batch, int N)
{
    int i = blockIdx.x * blockDim.x + threadIdx.x;
    int lane = threadIdx.x & 31;
    const bool is64 = batch_is64(batch, N);
    int g = -1;
    float e = 0.f;
    if (i < N) {
        g = get_batch(batch, i, is64);
        float m = __int_as_float(g_segmax[g]);
        e = expf(g_scores[i] - m);
        g_scores[i] = e;
    }
    float v = e;
#pragma unroll
    for (int d = 1; d < 32; d <<= 1) {
        float ov = __shfl_up_sync(0xffffffffu, v, d);
        int   og = __shfl_up_sync(0xffffffffu, g, d);
        if (lane >= d && og == g) v += ov;
    }
    int gn = __shfl_down_sync(0xffffffffu, g, 1);
    if (g >= 0 && (lane == 31 || gn != g))
        atomicAdd(&g_sumexp[g], v);
}

// -------- pass D: reciprocal --------
__global__ void k_inv()
{
    int i = blockIdx.x * blockDim.x + threadIdx.x;
    if (i < G) {
        float s = g_sumexp[i];
        g_inv[i] = (s > 0.f) ? 1.0f / s : 0.f;
    }
}

// -------- pass E: out[g] += x[i] * (exp_i * inv[g]), sorted-batch aware --------
__global__ void k_scatter(const float* __restrict__ x, const void* __restrict__ batch,
                          float* __restrict__ out, int N)
{
    int col = threadIdx.x;
    int i0 = blockIdx.x * NPB;
    if (i0 >= N) return;
    int i1 = min(i0 + NPB, N);
    const bool is64 = batch_is64(batch, N);

    int gfirst = get_batch(batch, i0, is64);
    int gcur = gfirst;
    float acc = 0.f;

    for (int i = i0; i < i1; i++) {
        int g = get_batch(batch, i, is64);
        if (g != gcur) {
            if (gcur == gfirst) atomicAdd(&out[(size_t)gcur * H + col], acc);
            else                out[(size_t)gcur * H + col] = acc;
            acc = 0.f;
            gcur = g;
        }
        float w = g_scores[i] * g_inv[g];
        acc += x[(size_t)i * H + col] * w;
    }
    atomicAdd(&out[(size_t)gcur * H + col], acc);
}

// -------- launch --------
extern "C" void kernel_launch(void* const* d_in, const int* in_sizes, int n_in,
                              void* d_out, int out_size)
{
    const float* x     = (const float*)d_in[0];
    const void*  batch = (const void*)d_in[1];
    const float* W1    = (const float*)d_in[2];
    const float* b1    = (const float*)d_in[3];
    const float* w2    = (const float*)d_in[4];
    float* out = (float*)d_out;

    int N = in_sizes[1];

    cudaFuncSetAttribute(k_gemm_mma, cudaFuncAttributeMaxDynamicSharedMemorySize, SM_TOT);

    int initBlocks = (out_size + 255) / 256;
    k_init<<<initBlocks, 256>>>(out, out_size);
    k_prep_w<<<H, H>>>(W1);
    k_gemm_mma<<<(N + BRM - 1) / BRM, 256, SM_TOT>>>(x, batch, b1, w2, N);
    k_exp_sum<<<(N + 255) / 256, 256>>>(batch, N);
    k_inv<<<(G + 255) / 256, 256>>>();
    k_scatter<<<(N + NPB - 1) / NPB, H>>>(x, batch, out, N);
}

// round 6
// speedup vs baseline: 2.2094x; 1.0520x over previous
#include <cuda_runtime.h>
#include <cuda_bf16.h>
#include <cstdint>
#include <cstddef>

#define H    256
#define G    4096
#define NPB  128      // nodes per scatter block
#define NMAX 500224   // capacity for per-node scratch (N = 500000)
#define BRM  64       // GEMM tile rows per CTA
#define STHB 144      // smem row stride in bytes (72 halves; 36 words -> LDSM conflict-free)

// SMEM layout (bytes): A_hi[2][64][72h], A_lo[2], B_hi[2][256][72h], B_lo[2], scb
#define SA_HI      0            // + buf*9216
#define SA_LO_OFF  18432        // A_lo = A_hi + 18432
#define SB_HI      36864        // + buf*36864
#define SB_LO_OFF  73728        // B_lo = B_hi + 73728
#define SM_SCB     184320
#define SM_TOT     185344

// -------- scratch (device globals: no allocation allowed) --------
__device__ float g_scores[NMAX];
__device__ int   g_segmax[G];
__device__ float g_sumexp[G];
__device__ float g_inv[G];
__device__ __nv_bfloat16 g_Wt_hi[H * H];   // W1^T hi: [n][k]
__device__ __nv_bfloat16 g_Wt_lo[H * H];   // W1^T lo: [n][k]

// -------- batch dtype detection (int32 vs int64) --------
__device__ __forceinline__ bool batch_is64(const void* b, int N) {
    return ((const int*)b)[N - 1] == 0;
}
__device__ __forceinline__ int get_batch(const void* b, int i, bool is64) {
    int g = is64 ? (int)((const long long*)b)[i] : ((const int*)b)[i];
    return (int)min((unsigned)g, (unsigned)(G - 1));
}

__device__ __forceinline__ uint32_t smem_u32(const void* p) {
    uint32_t a;
    asm("{ .reg .u64 t; cvta.to.shared.u64 t, %1; cvt.u32.u64 %0, t; }" : "=r"(a) : "l"(p));
    return a;
}

// -------- mma.sync m16n8k16 bf16 (baseline ISA) --------
__device__ __forceinline__ void mma16816(float* c, const uint32_t* a,
                                         uint32_t b0, uint32_t b1) {
    asm volatile(
        "mma.sync.aligned.m16n8k16.row.col.f32.bf16.bf16.f32 "
        "{%0,%1,%2,%3}, {%4,%5,%6,%7}, {%8,%9}, {%0,%1,%2,%3};"
        : "+f"(c[0]), "+f"(c[1]), "+f"(c[2]), "+f"(c[3])
        : "r"(a[0]), "r"(a[1]), "r"(a[2]), "r"(a[3]), "r"(b0), "r"(b1));
}
#define LDMX4(r, a) \
    asm volatile("ldmatrix.sync.aligned.m8n8.x4.shared.b16 {%0,%1,%2,%3}, [%4];" \
        : "=r"((r)[0]), "=r"((r)[1]), "=r"((r)[2]), "=r"((r)[3]) : "r"(a))
__device__ __forceinline__ void cp16(uint32_t dst, const void* src) {
    asm volatile("cp.async.cg.shared.global [%0], [%1], 16;" :: "r"(dst), "l"(src) : "memory");
}
#define CP_COMMIT() asm volatile("cp.async.commit_group;" ::: "memory")
#define CP_WAIT0()  asm volatile("cp.async.wait_group 0;" ::: "memory")

// pack 2 fp32 -> bf16x2 hi and lo words
__device__ __forceinline__ void split2(float v0, float v1, uint32_t& hi, uint32_t& lo) {
    __nv_bfloat16 h0 = __float2bfloat16(v0), h1 = __float2bfloat16(v1);
    float l0 = v0 - __bfloat162float(h0), l1 = v1 - __bfloat162float(h1);
    __nv_bfloat16 g0 = __float2bfloat16(l0), g1 = __float2bfloat16(l1);
    hi = ((uint32_t)__bfloat16_as_ushort(h1) << 16) | __bfloat16_as_ushort(h0);
    lo = ((uint32_t)__bfloat16_as_ushort(g1) << 16) | __bfloat16_as_ushort(g0);
}

// -------- pass 0: zero output + segment buffers --------
__global__ void k_init(float* __restrict__ out, int out_size) {
    int i = blockIdx.x * blockDim.x + threadIdx.x;
    if (i < out_size) out[i] = 0.0f;
    if (i < G) { g_segmax[i] = 0; g_sumexp[i] = 0.0f; }
}

// -------- prep: W1 [k][n] fp32 -> transposed bf16 hi/lo [n][k] --------
__global__ void k_prep_w(const float* __restrict__ W1) {
    int k = blockIdx.x, n = threadIdx.x;
    float w = W1[k * H + n];
    __nv_bfloat16 h = __float2bfloat16(w);
    float l = w - __bfloat162float(h);
    g_Wt_hi[n * H + k] = h;
    g_Wt_lo[n * H + k] = __float2bfloat16(l);
}

// -------- pass A: pipelined mma.sync GEMM (bf16 split) + fused epilogue --------
__global__ __launch_bounds__(512, 1)
void k_gemm_mma(const float* __restrict__ x, const void* __restrict__ batch,
                const float* __restrict__ b1, const float* __restrict__ w2, int N)
{
    extern __shared__ __align__(16) char smem[];
    const uint32_t sbase = smem_u32(smem);
    const int t    = threadIdx.x;
    const int lane = t & 31;
    const int wid  = t >> 5;
    const int wm   = wid & 3;        // M quarter (16 rows)
    const int wn   = wid >> 2;       // N quarter (64 cols)
    const int gq   = lane >> 2;
    const int tg   = lane & 3;
    const int rowbase = blockIdx.x * BRM;

    // per-lane ldmatrix address components
    const uint32_t a_off = (uint32_t)((wm * 16 + (lane & 15)) * STHB + (lane >> 4) * 16);
    const uint32_t b_off = (uint32_t)((wn * 64 + ((lane >> 4) << 3) + (lane & 7)) * STHB
                                      + ((lane >> 3) & 1) * 16);

    float C[8][4];
#pragma unroll
    for (int nt = 0; nt < 8; nt++)
#pragma unroll
        for (int r = 0; r < 4; r++) C[nt][r] = 0.f;

    // ---- A load/convert/store (512 threads, 2 float4 each = 64x64 fp32) ----
    auto loadA = [&](int k0, float4& v0, float4& v1) {
#pragma unroll
        for (int i = 0; i < 2; i++) {
            int idx = t + i * 512;
            int r = idx >> 4, q = idx & 15;
            int grow = rowbase + r;
            float4 v = make_float4(0.f, 0.f, 0.f, 0.f);
            if (grow < N)
                v = *reinterpret_cast<const float4*>(x + (size_t)grow * H + k0 + q * 4);
            if (i == 0) v0 = v; else v1 = v;
        }
    };
    auto storeA = [&](int buf, float4 v0, float4 v1) {
        char* base = smem + SA_HI + buf * 9216;
#pragma unroll
        for (int i = 0; i < 2; i++) {
            int idx = t + i * 512;
            int r = idx >> 4, q = idx & 15;
            float4 v = (i == 0) ? v0 : v1;
            uint32_t h0, l0, h1, l1;
            split2(v.x, v.y, h0, l0);
            split2(v.z, v.w, h1, l1);
            *reinterpret_cast<uint2*>(base + r * STHB + q * 8)             = make_uint2(h0, h1);
            *reinterpret_cast<uint2*>(base + SA_LO_OFF + r * STHB + q * 8) = make_uint2(l0, l1);
        }
    };
    auto loadB = [&](int k0, int buf) {
        uint32_t base = sbase + SB_HI + buf * 36864;
#pragma unroll
        for (int i = 0; i < 4; i++) {
            int idx = t + i * 512;            // 0..2047
            int n = idx >> 3, j = idx & 7;    // row n, 16B group (8 halves)
            uint32_t dst = base + (uint32_t)(n * STHB + j * 16);
            cp16(dst,             g_Wt_hi + n * H + k0 + j * 8);
            cp16(dst + SB_LO_OFF, g_Wt_lo + n * H + k0 + j * 8);
        }
    };

    // ---- prologue: fill buffer 0 ----
    {
        float4 a0, a1;
        loadA(0, a0, a1);
        loadB(0, 0);
        CP_COMMIT();
        storeA(0, a0, a1);
    }

    for (int c = 0; c < 4; c++) {
        const int buf = c & 1;
        const uint32_t sa = sbase + SA_HI + buf * 9216;
        const uint32_t sb = sbase + SB_HI + buf * 36864;

        CP_WAIT0();
        __syncthreads();           // buffer c ready (cp.async B + STS A)

        float4 a0, a1;
        const bool pf = (c < 3);
        if (pf) {
            loadB((c + 1) * 64, buf ^ 1);   // overlaps compute below
            CP_COMMIT();
            loadA((c + 1) * 64, a0, a1);    // LDG latency hidden by compute
        }

        // ---- compute chunk c: 4 k16-steps ----
#pragma unroll
        for (int ks = 0; ks < 4; ks++) {
            uint32_t Ah[4], Al[4];
            uint32_t aaddr = sa + a_off + ks * 32;
            LDMX4(Ah, aaddr);
            LDMX4(Al, aaddr + SA_LO_OFF);
#pragma unroll
            for (int p = 0; p < 4; p++) {
                uint32_t Bh[4], Bl[4];
                uint32_t baddr = sb + b_off + p * (16 * STHB) + ks * 32;
                LDMX4(Bh, baddr);
                LDMX4(Bl, baddr + SB_LO_OFF);
                mma16816(C[2 * p],     Ah, Bh[0], Bh[1]);
                mma16816(C[2 * p],     Al, Bh[0], Bh[1]);
                mma16816(C[2 * p],     Ah, Bl[0], Bl[1]);
                mma16816(C[2 * p + 1], Ah, Bh[2], Bh[3]);
                mma16816(C[2 * p + 1], Al, Bh[2], Bh[3]);
                mma16816(C[2 * p + 1], Ah, Bl[2], Bl[3]);
            }
        }

        if (pf) storeA(buf ^ 1, a0, a1);    // next-iter sync publishes it
    }

    // ---- epilogue: tanh + w2 dot, reduce over frag lanes + N-warps ----
    float (*scb)[64] = (float(*)[64])(smem + SM_SCB);
    {
        float p0 = 0.f, p1 = 0.f;           // rows wm*16+gq, +8
#pragma unroll
        for (int nt = 0; nt < 8; nt++) {
            int col0 = wn * 64 + nt * 8 + tg * 2;
            float bb0 = __ldg(b1 + col0), bb1 = __ldg(b1 + col0 + 1);
            float ww0 = __ldg(w2 + col0), ww1 = __ldg(w2 + col0 + 1);
            p0 += tanhf(C[nt][0] + bb0) * ww0 + tanhf(C[nt][1] + bb1) * ww1;
            p1 += tanhf(C[nt][2] + bb0) * ww0 + tanhf(C[nt][3] + bb1) * ww1;
        }
        p0 += __shfl_xor_sync(0xffffffffu, p0, 1);
        p0 += __shfl_xor_sync(0xffffffffu, p0, 2);
        p1 += __shfl_xor_sync(0xffffffffu, p1, 1);
        p1 += __shfl_xor_sync(0xffffffffu, p1, 2);
        __syncthreads();                    // smem buffers done; scb aliasing safe
        if (tg == 0) {
            int row = wm * 16 + gq;
            scb[wn][row]     = p0;
            scb[wn][row + 8] = p1;
        }
    }
    __syncthreads();
    if (t < 64) {
        float sc = scb[0][t] + scb[1][t] + scb[2][t] + scb[3][t];
        int grow = rowbase + t;
        if (grow < N) {
            g_scores[grow] = sc;
            if (sc > 0.f) {
                const bool is64 = batch_is64(batch, N);
                atomicMax(&g_segmax[get_batch(batch, grow, is64)], __float_as_int(sc));
            }
        }
    }
}

// -------- pass C: exp(score - segmax), warp-segmented sum into sumexp --------
__global__ void k_exp_sum(const void* __restrict__ batch, int N)
{
    int i = blockIdx.x * blockDim.x + threadIdx.x;
    int lane = threadIdx.x & 31;
    const bool is64 = batch_is64(batch, N);
    int g = -1;
    float e = 0.f;
    if (i < N) {
        g = get_batch(batch, i, is64);
        float m = __int_as_float(g_segmax[g]);
        e = expf(g_scores[i] - m);
        g_scores[i] = e;
    }
    float v = e;
#pragma unroll
    for (int d = 1; d < 32; d <<= 1) {
        float ov = __shfl_up_sync(0xffffffffu, v, d);
        int   og = __shfl_up_sync(0xffffffffu, g, d);
        if (lane >= d && og == g) v += ov;
    }
    int gn = __shfl_down_sync(0xffffffffu, g, 1);
    if (g >= 0 && (lane == 31 || gn != g))
        atomicAdd(&g_sumexp[g], v);
}

// -------- pass D: reciprocal --------
__global__ void k_inv()
{
    int i = blockIdx.x * blockDim.x + threadIdx.x;
    if (i < G) {
        float s = g_sumexp[i];
        g_inv[i] = (s > 0.f) ? 1.0f / s : 0.f;
    }
}

// -------- pass E: out[g] += x[i] * (exp_i * inv[g]); float4, 4 row-partitions --------
__global__ void k_scatter(const float* __restrict__ x, const void* __restrict__ batch,
                          float* __restrict__ out, int N)
{
    const int tc = threadIdx.x & 63;       // column group: cols [4tc, 4tc+3]
    const int tp = threadIdx.x >> 6;       // row partition 0..3 (32 rows each)
    const int col = tc * 4;
    int i0 = blockIdx.x * NPB + tp * 32;
    if (i0 >= N) return;
    int i1 = min(i0 + 32, N);
    const bool is64 = batch_is64(batch, N);

    int gfirst = get_batch(batch, i0, is64);
    int gcur = gfirst;
    float4 acc = make_float4(0.f, 0.f, 0.f, 0.f);

    for (int i = i0; i < i1; i++) {
        int g = get_batch(batch, i, is64);
        if (g != gcur) {
            float* o = out + (size_t)gcur * H + col;
            if (gcur == gfirst) {
                atomicAdd(o + 0, acc.x); atomicAdd(o + 1, acc.y);
                atomicAdd(o + 2, acc.z); atomicAdd(o + 3, acc.w);
            } else {
                *reinterpret_cast<float4*>(o) = acc;  // exclusive interior graph
            }
            acc = make_float4(0.f, 0.f, 0.f, 0.f);
            gcur = g;
        }
        float w = g_scores[i] * g_inv[g];
        float4 v = *reinterpret_cast<const float4*>(x + (size_t)i * H + col);
        acc.x += v.x * w; acc.y += v.y * w; acc.z += v.z * w; acc.w += v.w * w;
    }
    float* o = out + (size_t)gcur * H + col;
    atomicAdd(o + 0, acc.x); atomicAdd(o + 1, acc.y);
    atomicAdd(o + 2, acc.z); atomicAdd(o + 3, acc.w);
}

// -------- launch --------
extern "C" void kernel_launch(void* const* d_in, const int* in_sizes, int n_in,
                              void* d_out, int out_size)
{
    const float* x     = (const float*)d_in[0];
    const void*  batch = (const void*)d_in[1];
    const float* W1    = (const float*)d_in[2];
    const float* b1    = (const float*)d_in[3];
    const float* w2    = (const float*)d_in[4];
    float* out = (float*)d_out;

    int N = in_sizes[1];

    cudaFuncSetAttribute(k_gemm_mma, cudaFuncAttributeMaxDynamicSharedMemorySize, SM_TOT);

    int initBlocks = (out_size + 255) / 256;
    k_init<<<initBlocks, 256>>>(out, out_size);
    k_prep_w<<<H, H>>>(W1);
    k_gemm_mma<<<(N + BRM - 1) / BRM, 512, SM_TOT>>>(x, batch, b1, w2, N);
    k_exp_sum<<<(N + 255) / 256, 256>>>(batch, N);
    k_inv<<<(G + 255) / 256, 256>>>();
    k_scatter<<<(N + NPB - 1) / NPB, 256>>>(x, batch, out, N);
}

// round 7
// speedup vs baseline: 2.6093x; 1.1810x over previous
#include <cuda_runtime.h>
#include <cuda_bf16.h>
#include <cstdint>
#include <cstddef>

#define H    256
#define G    4096
#define NPB  128      // nodes per scatter block
#define NMAX 500224   // capacity for per-node scratch (N = 500000)
#define BRM  128      // GEMM tile rows per CTA
#define STHB 144      // smem row stride in bytes (72 halves; conflict-free LDSM)

// SMEM layout (bytes)
#define SA_HI      0            // + buf*18432
#define SA_LO_OFF  36864        // A_lo region = A_hi + 36864
#define SB_HI      73728        // + buf*36864
#define SB_LO_OFF  73728        // B_lo = B_hi + 73728
#define SM_SCB     221184
#define SM_TOT     223232

// -------- scratch (device globals: no allocation allowed) --------
__device__ float g_scores[NMAX];
__device__ int   g_segmax[G];
__device__ float g_sumexp[G];
__device__ float g_inv[G];
__device__ __nv_bfloat16 g_Wt_hi[H * H];   // W1^T hi: [n][k]
__device__ __nv_bfloat16 g_Wt_lo[H * H];   // W1^T lo: [n][k]

// -------- batch dtype detection (int32 vs int64) --------
__device__ __forceinline__ bool batch_is64(const void* b, int N) {
    return ((const int*)b)[N - 1] == 0;
}
__device__ __forceinline__ int get_batch(const void* b, int i, bool is64) {
    int g = is64 ? (int)((const long long*)b)[i] : ((const int*)b)[i];
    return (int)min((unsigned)g, (unsigned)(G - 1));
}

__device__ __forceinline__ uint32_t smem_u32(const void* p) {
    uint32_t a;
    asm("{ .reg .u64 t; cvta.to.shared.u64 t, %1; cvt.u32.u64 %0, t; }" : "=r"(a) : "l"(p));
    return a;
}

// -------- mma.sync m16n8k16 bf16 (baseline ISA) --------
__device__ __forceinline__ void mma16816(float* c, const uint32_t* a,
                                         uint32_t b0, uint32_t b1) {
    asm volatile(
        "mma.sync.aligned.m16n8k16.row.col.f32.bf16.bf16.f32 "
        "{%0,%1,%2,%3}, {%4,%5,%6,%7}, {%8,%9}, {%0,%1,%2,%3};"
        : "+f"(c[0]), "+f"(c[1]), "+f"(c[2]), "+f"(c[3])
        : "r"(a[0]), "r"(a[1]), "r"(a[2]), "r"(a[3]), "r"(b0), "r"(b1));
}
#define LDMX4(r, a) \
    asm volatile("ldmatrix.sync.aligned.m8n8.x4.shared.b16 {%0,%1,%2,%3}, [%4];" \
        : "=r"((r)[0]), "=r"((r)[1]), "=r"((r)[2]), "=r"((r)[3]) : "r"(a))
__device__ __forceinline__ void cp16(uint32_t dst, const void* src) {
    asm volatile("cp.async.cg.shared.global [%0], [%1], 16;" :: "r"(dst), "l"(src) : "memory");
}
#define CP_COMMIT() asm volatile("cp.async.commit_group;" ::: "memory")
#define CP_WAIT0()  asm volatile("cp.async.wait_group 0;" ::: "memory")

// pack 2 fp32 -> bf16x2 hi and lo words
__device__ __forceinline__ void split2(float v0, float v1, uint32_t& hi, uint32_t& lo) {
    __nv_bfloat16 h0 = __float2bfloat16(v0), h1 = __float2bfloat16(v1);
    float l0 = v0 - __bfloat162float(h0), l1 = v1 - __bfloat162float(h1);
    __nv_bfloat16 g0 = __float2bfloat16(l0), g1 = __float2bfloat16(l1);
    hi = ((uint32_t)__bfloat16_as_ushort(h1) << 16) | __bfloat16_as_ushort(h0);
    lo = ((uint32_t)__bfloat16_as_ushort(g1) << 16) | __bfloat16_as_ushort(g0);
}

// -------- init split in two so the GEMM lands at launch position 3 (ncu) ----
__global__ void k_init_out(float* __restrict__ out, int out_size) {
    int i = blockIdx.x * blockDim.x + threadIdx.x;
    if (i < out_size) out[i] = 0.0f;
}
__global__ void k_init_seg() {
    int i = blockIdx.x * blockDim.x + threadIdx.x;
    if (i < G) { g_segmax[i] = 0; g_sumexp[i] = 0.0f; }
}

// -------- prep: W1 [k][n] fp32 -> transposed bf16 hi/lo [n][k] --------
__global__ void k_prep_w(const float* __restrict__ W1) {
    int k = blockIdx.x, n = threadIdx.x;
    float w = W1[k * H + n];
    __nv_bfloat16 h = __float2bfloat16(w);
    float l = w - __bfloat162float(h);
    g_Wt_hi[n * H + k] = h;
    g_Wt_lo[n * H + k] = __float2bfloat16(l);
}

// -------- pass A: pipelined mma.sync GEMM (bf16 split), M=128 tile --------
__global__ __launch_bounds__(512, 1)
void k_gemm_mma(const float* __restrict__ x, const void* __restrict__ batch,
                const float* __restrict__ b1, const float* __restrict__ w2, int N)
{
    extern __shared__ __align__(16) char smem[];
    const uint32_t sbase = smem_u32(smem);
    const int t    = threadIdx.x;
    const int lane = t & 31;
    const int wid  = t >> 5;
    const int wm   = wid & 3;        // M quarter (32 rows)
    const int wn   = wid >> 2;       // N quarter (64 cols)
    const int gq   = lane >> 2;
    const int tg   = lane & 3;
    const int rowbase = blockIdx.x * BRM;

    const uint32_t a_off = (uint32_t)((wm * 32 + (lane & 15)) * STHB + (lane >> 4) * 16);
    const uint32_t b_off = (uint32_t)((wn * 64 + ((lane >> 4) << 3) + (lane & 7)) * STHB
                                      + ((lane >> 3) & 1) * 16);

    float C[2][8][4];
#pragma unroll
    for (int mt = 0; mt < 2; mt++)
#pragma unroll
        for (int nt = 0; nt < 8; nt++)
#pragma unroll
            for (int r = 0; r < 4; r++) C[mt][nt][r] = 0.f;

    // ---- A load/convert/store (512 threads, 4 float4 each = 128x64 fp32) ----
    auto loadA = [&](int k0, float4* v) {
#pragma unroll
        for (int i = 0; i < 4; i++) {
            int idx = t + i * 512;            // 0..2047
            int r = idx >> 4, q = idx & 15;
            int grow = rowbase + r;
            float4 vv = make_float4(0.f, 0.f, 0.f, 0.f);
            if (grow < N)
                vv = *reinterpret_cast<const float4*>(x + (size_t)grow * H + k0 + q * 4);
            v[i] = vv;
        }
    };
    auto storeA = [&](int buf, const float4* v) {
        char* base = smem + SA_HI + buf * 18432;
#pragma unroll
        for (int i = 0; i < 4; i++) {
            int idx = t + i * 512;
            int r = idx >> 4, q = idx & 15;
            uint32_t h0, l0, h1, l1;
            split2(v[i].x, v[i].y, h0, l0);
            split2(v[i].z, v[i].w, h1, l1);
            *reinterpret_cast<uint2*>(base + r * STHB + q * 8)             = make_uint2(h0, h1);
            *reinterpret_cast<uint2*>(base + SA_LO_OFF + r * STHB + q * 8) = make_uint2(l0, l1);
        }
    };
    auto loadB = [&](int k0, int buf) {
        uint32_t base = sbase + SB_HI + buf * 36864;
#pragma unroll
        for (int i = 0; i < 4; i++) {
            int idx = t + i * 512;            // 0..2047
            int n = idx >> 3, j = idx & 7;
            uint32_t dst = base + (uint32_t)(n * STHB + j * 16);
            cp16(dst,             g_Wt_hi + n * H + k0 + j * 8);
            cp16(dst + SB_LO_OFF, g_Wt_lo + n * H + k0 + j * 8);
        }
    };

    // ---- prologue: fill buffer 0 ----
    {
        float4 a[4];
        loadA(0, a);
        loadB(0, 0);
        CP_COMMIT();
        storeA(0, a);
    }

    for (int c = 0; c < 4; c++) {
        const int buf = c & 1;
        const uint32_t sa = sbase + SA_HI + buf * 18432;
        const uint32_t sb = sbase + SB_HI + buf * 36864;

        CP_WAIT0();
        __syncthreads();           // buffer c ready (cp.async B + STS A)

        float4 a[4];
        const bool pf = (c < 3);
        if (pf) {
            loadB((c + 1) * 64, buf ^ 1);   // overlaps compute below
            CP_COMMIT();
            loadA((c + 1) * 64, a);         // LDG latency hidden by compute
        }

        // ---- compute chunk c: 4 k16-steps ----
#pragma unroll
        for (int ks = 0; ks < 4; ks++) {
            uint32_t Ah[2][4], Al[2][4];
#pragma unroll
            for (int mt = 0; mt < 2; mt++) {
                uint32_t aaddr = sa + a_off + mt * (16 * STHB) + ks * 32;
                LDMX4(Ah[mt], aaddr);
                LDMX4(Al[mt], aaddr + SA_LO_OFF);
            }
#pragma unroll
            for (int p = 0; p < 4; p++) {
                uint32_t Bh[4], Bl[4];
                uint32_t baddr = sb + b_off + p * (16 * STHB) + ks * 32;
                LDMX4(Bh, baddr);
                LDMX4(Bl, baddr + SB_LO_OFF);
#pragma unroll
                for (int mt = 0; mt < 2; mt++) {
                    mma16816(C[mt][2 * p],     Ah[mt], Bh[0], Bh[1]);
                    mma16816(C[mt][2 * p],     Al[mt], Bh[0], Bh[1]);
                    mma16816(C[mt][2 * p],     Ah[mt], Bl[0], Bl[1]);
                    mma16816(C[mt][2 * p + 1], Ah[mt], Bh[2], Bh[3]);
                    mma16816(C[mt][2 * p + 1], Al[mt], Bh[2], Bh[3]);
                    mma16816(C[mt][2 * p + 1], Ah[mt], Bl[2], Bl[3]);
                }
            }
        }

        if (pf) storeA(buf ^ 1, a);    // next-iter sync publishes it
    }

    // ---- epilogue: tanh + w2 dot, reduce over frag lanes + N-warps ----
    float (*scb)[128] = (float(*)[128])(smem + SM_SCB);
#pragma unroll
    for (int mt = 0; mt < 2; mt++) {
        float p0 = 0.f, p1 = 0.f;           // rows wm*32+mt*16+gq, +8
#pragma unroll
        for (int nt = 0; nt < 8; nt++) {
            int col0 = wn * 64 + nt * 8 + tg * 2;
            float bb0 = __ldg(b1 + col0), bb1 = __ldg(b1 + col0 + 1);
            float ww0 = __ldg(w2 + col0), ww1 = __ldg(w2 + col0 + 1);
            p0 += tanhf(C[mt][nt][0] + bb0) * ww0 + tanhf(C[mt][nt][1] + bb1) * ww1;
            p1 += tanhf(C[mt][nt][2] + bb0) * ww0 + tanhf(C[mt][nt][3] + bb1) * ww1;
        }
        p0 += __shfl_xor_sync(0xffffffffu, p0, 1);
        p0 += __shfl_xor_sync(0xffffffffu, p0, 2);
        p1 += __shfl_xor_sync(0xffffffffu, p1, 1);
        p1 += __shfl_xor_sync(0xffffffffu, p1, 2);
        if (tg == 0) {
            int row = wm * 32 + mt * 16 + gq;
            scb[wn][row]     = p0;
            scb[wn][row + 8] = p1;
        }
    }
    __syncthreads();
    if (t < 128) {
        float sc = scb[0][t] + scb[1][t] + scb[2][t] + scb[3][t];
        int grow = rowbase + t;
        if (grow < N) {
            g_scores[grow] = sc;
            if (sc > 0.f) {
                const bool is64 = batch_is64(batch, N);
                atomicMax(&g_segmax[get_batch(batch, grow, is64)], __float_as_int(sc));
            }
        }
    }
}

// -------- pass C: exp(score - segmax), warp-segmented sum into sumexp --------
__global__ void k_exp_sum(const void* __restrict__ batch, int N)
{
    int i = blockIdx.x * blockDim.x + threadIdx.x;
    int lane = threadIdx.x & 31;
    const bool is64 = batch_is64(batch, N);
    int g = -1;
    float e = 0.f;
    if (i < N) {
        g = get_batch(batch, i, is64);
        float m = __int_as_float(g_segmax[g]);
        e = expf(g_scores[i] - m);
        g_scores[i] = e;
    }
    float v = e;
#pragma unroll
    for (int d = 1; d < 32; d <<= 1) {
        float ov = __shfl_up_sync(0xffffffffu, v, d);
        int   og = __shfl_up_sync(0xffffffffu, g, d);
        if (lane >= d && og == g) v += ov;
    }
    int gn = __shfl_down_sync(0xffffffffu, g, 1);
    if (g >= 0 && (lane == 31 || gn != g))
        atomicAdd(&g_sumexp[g], v);
}

// -------- pass D: reciprocal --------
__global__ void k_inv()
{
    int i = blockIdx.x * blockDim.x + threadIdx.x;
    if (i < G) {
        float s = g_sumexp[i];
        g_inv[i] = (s > 0.f) ? 1.0f / s : 0.f;
    }
}

// -------- pass E: out[g] += x[i] * (exp_i * inv[g]); float4, 4 row-partitions --------
__global__ void k_scatter(const float* __restrict__ x, const void* __restrict__ batch,
                          float* __restrict__ out, int N)
{
    const int tc = threadIdx.x & 63;       // column group: cols [4tc, 4tc+3]
    const int tp = threadIdx.x >> 6;       // row partition 0..3 (32 rows each)
    const int col = tc * 4;
    int i0 = blockIdx.x * NPB + tp * 32;
    if (i0 >= N) return;
    int i1 = min(i0 + 32, N);
    const bool is64 = batch_is64(batch, N);

    int gfirst = get_batch(batch, i0, is64);
    int gcur = gfirst;
    float4 acc = make_float4(0.f, 0.f, 0.f, 0.f);

    for (int i = i0; i < i1; i++) {
        int g = get_batch(batch, i, is64);
        if (g != gcur) {
            float* o = out + (size_t)gcur * H + col;
            if (gcur == gfirst) {
                atomicAdd(o + 0, acc.x); atomicAdd(o + 1, acc.y);
                atomicAdd(o + 2, acc.z); atomicAdd(o + 3, acc.w);
            } else {
                *reinterpret_cast<float4*>(o) = acc;  // exclusive interior graph
            }
            acc = make_float4(0.f, 0.f, 0.f, 0.f);
            gcur = g;
        }
        float w = g_scores[i] * g_inv[g];
        float4 v = *reinterpret_cast<const float4*>(x + (size_t)i * H + col);
        acc.x += v.x * w; acc.y += v.y * w; acc.z += v.z * w; acc.w += v.w * w;
    }
    float* o = out + (size_t)gcur * H + col;
    atomicAdd(o + 0, acc.x); atomicAdd(o + 1, acc.y);
    atomicAdd(o + 2, acc.z); atomicAdd(o + 3, acc.w);
}

// -------- launch --------
extern "C" void kernel_launch(void* const* d_in, const int* in_sizes, int n_in,
                              void* d_out, int out_size)
{
    const float* x     = (const float*)d_in[0];
    const void*  batch = (const void*)d_in[1];
    const float* W1    = (const float*)d_in[2];
    const float* b1    = (const float*)d_in[3];
    const float* w2    = (const float*)d_in[4];
    float* out = (float*)d_out;

    int N = in_sizes[1];

    cudaFuncSetAttribute(k_gemm_mma, cudaFuncAttributeMaxDynamicSharedMemorySize, SM_TOT);

    int initBlocks = (out_size + 255) / 256;
    k_init_out<<<initBlocks, 256>>>(out, out_size);   // pos 0
    k_init_seg<<<16, 256>>>();                        // pos 1
    k_prep_w<<<H, H>>>(W1);                           // pos 2
    k_gemm_mma<<<(N + BRM - 1) / BRM, 512, SM_TOT>>>(x, batch, b1, w2, N);  // pos 3 (ncu target)
    k_exp_sum<<<(N + 255) / 256, 256>>>(batch, N);
    k_inv<<<(G + 255) / 256, 256>>>();
    k_scatter<<<(N + NPB - 1) / NPB, 256>>>(x, batch, out, N);
}